// round 5
// baseline (speedup 1.0000x reference)
#include <cuda_runtime.h>

// Problem constants (match reference)
#define NVX 200
#define NVY 200
#define NVZ 16
#define N_VOX (NVX * NVY * NVZ)          // 640000
#define FEAT_DIM 17
#define ACC_STRIDE 20                    // 17 feats + density + 2 pad (16B alignment)
#define VOXEL 0.4f

// Scratch accumulator: [voxel][20] floats, 16B aligned rows. 51.2 MB static.
__device__ __align__(16) float g_accum[(size_t)N_VOX * ACC_STRIDE];

// ---------------------------------------------------------------------------
// Zero the accumulator (float4 grid-stride)
// ---------------------------------------------------------------------------
__global__ void zero_kernel() {
    int i = blockIdx.x * blockDim.x + threadIdx.x;
    float4* p = reinterpret_cast<float4*>(g_accum);
    const int n4 = N_VOX * ACC_STRIDE / 4;
    const float4 z = make_float4(0.f, 0.f, 0.f, 0.f);
    for (; i < n4; i += gridDim.x * blockDim.x) p[i] = z;
}

// ---------------------------------------------------------------------------
// Vectorized global reduction (no return value -> REDG)
// ---------------------------------------------------------------------------
__device__ __forceinline__ void red4(float* p, float a, float b, float c, float d) {
    asm volatile("red.global.add.v4.f32 [%0], {%1,%2,%3,%4};"
                 :: "l"(p), "f"(a), "f"(b), "f"(c), "f"(d) : "memory");
}

// ---------------------------------------------------------------------------
// Splat: one warp per gaussian, lanes stride over the 343-voxel stencil.
// ---------------------------------------------------------------------------
__global__ void __launch_bounds__(256) splat_kernel(
    const float* __restrict__ means,
    const float* __restrict__ opac,
    const float* __restrict__ scales,
    const float* __restrict__ rots,
    const float* __restrict__ feats,
    int n)
{
    int g    = (blockIdx.x * blockDim.x + threadIdx.x) >> 5;
    int lane = threadIdx.x & 31;
    if (g >= n) return;

    // Broadcast loads (same address across warp -> single L1 transaction)
    float mx = means[3*g+0], my = means[3*g+1], mz = means[3*g+2];
    float op = opac[g];
    float sx = scales[3*g+0], sy = scales[3*g+1], sz = scales[3*g+2];
    float q0 = rots[4*g+0], q1 = rots[4*g+1], q2 = rots[4*g+2], q3 = rots[4*g+3];

    // Normalized quaternion -> rotation matrix
    float qn = rsqrtf(q0*q0 + q1*q1 + q2*q2 + q3*q3 + 1e-8f);
    float r = q0*qn, x = q1*qn, y = q2*qn, z = q3*qn;

    float R00 = 1.f - 2.f*(y*y + z*z);
    float R01 = 2.f*(x*y - r*z);
    float R02 = 2.f*(x*z + r*y);
    float R10 = 2.f*(x*y + r*z);
    float R11 = 1.f - 2.f*(x*x + z*z);
    float R12 = 2.f*(y*z - r*x);
    float R20 = 2.f*(x*z - r*y);
    float R21 = 2.f*(y*z + r*x);
    float R22 = 1.f - 2.f*(x*x + y*y);

    // Cov = R^T diag(s^2) R  (R orthogonal)  =>  CovInv = R^T diag(1/s^2) R
    float i0 = 1.f/(sx*sx), i1 = 1.f/(sy*sy), i2 = 1.f/(sz*sz);

    float cxx = R00*R00*i0 + R10*R10*i1 + R20*R20*i2;
    float cyy = R01*R01*i0 + R11*R11*i1 + R21*R21*i2;
    float czz = R02*R02*i0 + R12*R12*i1 + R22*R22*i2;
    float cxy = R00*R01*i0 + R10*R11*i1 + R20*R21*i2;
    float cyz = R01*R02*i0 + R11*R12*i1 + R21*R22*i2;
    float cxz = R00*R02*i0 + R10*R12*i1 + R20*R22*i2;

    float smax = fmaxf(sx, fmaxf(sy, sz));
    int rad = (int)ceilf(smax * 3.0f / VOXEL);
    if (rad < 1) rad = 1;

    int mix = (int)floorf((mx + 40.f) / VOXEL);
    int miy = (int)floorf((my + 40.f) / VOXEL);
    int miz = (int)floorf((mz +  1.f) / VOXEL);

    float f0  = feats[17*g+0],  f1  = feats[17*g+1],  f2  = feats[17*g+2];
    float f3  = feats[17*g+3],  f4  = feats[17*g+4],  f5  = feats[17*g+5];
    float f6  = feats[17*g+6],  f7  = feats[17*g+7],  f8  = feats[17*g+8];
    float f9  = feats[17*g+9],  f10 = feats[17*g+10], f11 = feats[17*g+11];
    float f12 = feats[17*g+12], f13 = feats[17*g+13], f14 = feats[17*g+14];
    float f15 = feats[17*g+15], f16 = feats[17*g+16];

    for (int t = lane; t < 343; t += 32) {
        int ok = t % 7 - 3;
        int oj = (t / 7) % 7 - 3;
        int oi = t / 49 - 3;

        int m = max(abs(oi), max(abs(oj), abs(ok)));
        if (m > rad) continue;

        int ix = mix + oi, iy = miy + oj, iz = miz + ok;
        if ((unsigned)ix >= (unsigned)NVX ||
            (unsigned)iy >= (unsigned)NVY ||
            (unsigned)iz >= (unsigned)NVZ) continue;

        // center = idx*VOXEL + vol_min + 0.5*VOXEL
        float dx = mx - ((float)ix * VOXEL - 40.f + 0.2f);
        float dy = my - ((float)iy * VOXEL - 40.f + 0.2f);
        float dz = mz - ((float)iz * VOXEL -  1.f + 0.2f);

        float pw = -0.5f * (cxx*dx*dx + cyy*dy*dy + czz*dz*dz)
                         - (cxy*dx*dy + cyz*dy*dz + cxz*dx*dz);
        float c = op * __expf(pw);

        float* p = g_accum + (size_t)((ix*NVY + iy)*NVZ + iz) * ACC_STRIDE;
        red4(p,      c*f0,  c*f1,  c*f2,  c*f3);
        red4(p + 4,  c*f4,  c*f5,  c*f6,  c*f7);
        red4(p + 8,  c*f8,  c*f9,  c*f10, c*f11);
        red4(p + 12, c*f12, c*f13, c*f14, c*f15);
        atomicAdd(p + 16, c*f16);   // feat 16
        atomicAdd(p + 17, c);       // density
    }
}

// ---------------------------------------------------------------------------
// Finalize: out[0 : 640000]           = density
//           out[640000 : 640000+17*v] = feat_acc / max(density, EPS)
// ---------------------------------------------------------------------------
__global__ void finalize_kernel(float* __restrict__ out) {
    int v = blockIdx.x * blockDim.x + threadIdx.x;
    if (v >= N_VOX) return;

    const float* p = g_accum + (size_t)v * ACC_STRIDE;
    float4 a  = *reinterpret_cast<const float4*>(p);
    float4 b  = *reinterpret_cast<const float4*>(p + 4);
    float4 cc = *reinterpret_cast<const float4*>(p + 8);
    float4 dd = *reinterpret_cast<const float4*>(p + 12);
    float  e  = p[16];
    float  d  = p[17];

    out[v] = d;
    float inv = 1.f / fmaxf(d, 1e-6f);

    float* fo = out + N_VOX + (size_t)v * FEAT_DIM;
    fo[0]  = a.x  * inv;  fo[1]  = a.y  * inv;  fo[2]  = a.z  * inv;  fo[3]  = a.w  * inv;
    fo[4]  = b.x  * inv;  fo[5]  = b.y  * inv;  fo[6]  = b.z  * inv;  fo[7]  = b.w  * inv;
    fo[8]  = cc.x * inv;  fo[9]  = cc.y * inv;  fo[10] = cc.z * inv;  fo[11] = cc.w * inv;
    fo[12] = dd.x * inv;  fo[13] = dd.y * inv;  fo[14] = dd.z * inv;  fo[15] = dd.w * inv;
    fo[16] = e    * inv;
}

// ---------------------------------------------------------------------------
// Launch
// ---------------------------------------------------------------------------
extern "C" void kernel_launch(void* const* d_in, const int* in_sizes, int n_in,
                              void* d_out, int out_size) {
    const float* means  = (const float*)d_in[0];
    const float* opac   = (const float*)d_in[1];
    const float* scales = (const float*)d_in[2];
    const float* rots   = (const float*)d_in[3];
    const float* feats  = (const float*)d_in[4];
    int n = in_sizes[1];  // opacities: one per gaussian

    zero_kernel<<<2048, 256>>>();

    int threads = n * 32;                       // one warp per gaussian
    int blocks  = (threads + 255) / 256;
    splat_kernel<<<blocks, 256>>>(means, opac, scales, rots, feats, n);

    finalize_kernel<<<(N_VOX + 255) / 256, 256>>>((float*)d_out);
}

// round 6
// speedup vs baseline: 1.4543x; 1.4543x over previous
#include <cuda_runtime.h>

// Problem constants (match reference)
#define NVX 200
#define NVY 200
#define NVZ 16
#define N_VOX (NVX * NVY * NVZ)          // 640000
#define FEAT_DIM 17
#define VOXEL 0.4f

// Accumulator layout: [column = ix*NVY+iy][group 0..4][iz 0..15][4 floats]
//   group 0..3 : feats 0..15  (4 per group)
//   group 4    : {f16, density, pad, pad} per z (only first 2 used, v2 red)
// Z-cells of one group are 16B apart and contiguous -> warp lanes covering a
// stencil z-column coalesce into 1-2 L2 lines per red instruction.
#define NGRP 5
#define COL_FLOATS (NGRP * NVZ * 4)      // 320 floats per column
__device__ __align__(16) float g_accum[(size_t)NVX * NVY * COL_FLOATS]; // 51.2 MB

// ---------------------------------------------------------------------------
// Zero the accumulator (float4 grid-stride)
// ---------------------------------------------------------------------------
__global__ void zero_kernel() {
    int i = blockIdx.x * blockDim.x + threadIdx.x;
    float4* p = reinterpret_cast<float4*>(g_accum);
    const int n4 = NVX * NVY * COL_FLOATS / 4;
    const float4 z = make_float4(0.f, 0.f, 0.f, 0.f);
    for (; i < n4; i += gridDim.x * blockDim.x) p[i] = z;
}

// ---------------------------------------------------------------------------
// Vectorized global reductions (no return value -> REDG)
// ---------------------------------------------------------------------------
__device__ __forceinline__ void red4(float* p, float a, float b, float c, float d) {
    asm volatile("red.global.add.v4.f32 [%0], {%1,%2,%3,%4};"
                 :: "l"(p), "f"(a), "f"(b), "f"(c), "f"(d) : "memory");
}
__device__ __forceinline__ void red2(float* p, float a, float b) {
    asm volatile("red.global.add.v2.f32 [%0], {%1,%2};"
                 :: "l"(p), "f"(a), "f"(b) : "memory");
}

// ---------------------------------------------------------------------------
// Per-gaussian parameters (uniform across the warp)
// ---------------------------------------------------------------------------
struct GParams {
    float mx, my, mz, op;
    float cxx, cyy, czz, cxy, cyz, cxz;
    int   mix, miy, miz;
    float f[FEAT_DIM];
};

// Tight stencil loop specialized on radius: iterates only the (2R+1)^3 cells
// that can actually contribute (1 / 4 / 11 warp-iterations for R = 1/2/3).
template <int RAD>
__device__ __forceinline__ void splat_cells(const GParams& p, int lane) {
    constexpr int W = 2 * RAD + 1;
    constexpr int CELLS = W * W * W;

    #pragma unroll 1
    for (int t = lane; t < CELLS; t += 32) {
        int ok = t % W - RAD;
        int oj = (t / W) % W - RAD;
        int oi = t / (W * W) - RAD;

        int ix = p.mix + oi, iy = p.miy + oj, iz = p.miz + ok;
        if ((unsigned)ix >= (unsigned)NVX ||
            (unsigned)iy >= (unsigned)NVY ||
            (unsigned)iz >= (unsigned)NVZ) continue;

        // center = idx*VOXEL + vol_min + 0.5*VOXEL
        float dx = p.mx - ((float)ix * VOXEL - 40.f + 0.2f);
        float dy = p.my - ((float)iy * VOXEL - 40.f + 0.2f);
        float dz = p.mz - ((float)iz * VOXEL -  1.f + 0.2f);

        float pw = -0.5f * (p.cxx*dx*dx + p.cyy*dy*dy + p.czz*dz*dz)
                         - (p.cxy*dx*dy + p.cyz*dy*dz + p.cxz*dx*dz);
        float c = p.op * __expf(pw);

        float* base = g_accum + (size_t)(ix * NVY + iy) * COL_FLOATS + iz * 4;
        red4(base,        c*p.f[0],  c*p.f[1],  c*p.f[2],  c*p.f[3]);
        red4(base +  64,  c*p.f[4],  c*p.f[5],  c*p.f[6],  c*p.f[7]);
        red4(base + 128,  c*p.f[8],  c*p.f[9],  c*p.f[10], c*p.f[11]);
        red4(base + 192,  c*p.f[12], c*p.f[13], c*p.f[14], c*p.f[15]);
        red2(base + 256,  c*p.f[16], c);   // {feat16, density}
    }
}

// ---------------------------------------------------------------------------
// Splat: one warp per gaussian, lanes stride over the stencil.
// ---------------------------------------------------------------------------
__global__ void __launch_bounds__(256) splat_kernel(
    const float* __restrict__ means,
    const float* __restrict__ opac,
    const float* __restrict__ scales,
    const float* __restrict__ rots,
    const float* __restrict__ feats,
    int n)
{
    int g    = (blockIdx.x * blockDim.x + threadIdx.x) >> 5;
    int lane = threadIdx.x & 31;
    if (g >= n) return;

    // Broadcast loads (same address across warp -> single L1 transaction)
    GParams p;
    p.mx = means[3*g+0]; p.my = means[3*g+1]; p.mz = means[3*g+2];
    p.op = opac[g];
    float sx = scales[3*g+0], sy = scales[3*g+1], sz = scales[3*g+2];
    float q0 = rots[4*g+0], q1 = rots[4*g+1], q2 = rots[4*g+2], q3 = rots[4*g+3];

    // Normalized quaternion -> rotation matrix
    float qn = rsqrtf(q0*q0 + q1*q1 + q2*q2 + q3*q3 + 1e-8f);
    float r = q0*qn, x = q1*qn, y = q2*qn, z = q3*qn;

    float R00 = 1.f - 2.f*(y*y + z*z);
    float R01 = 2.f*(x*y - r*z);
    float R02 = 2.f*(x*z + r*y);
    float R10 = 2.f*(x*y + r*z);
    float R11 = 1.f - 2.f*(x*x + z*z);
    float R12 = 2.f*(y*z - r*x);
    float R20 = 2.f*(x*z - r*y);
    float R21 = 2.f*(y*z + r*x);
    float R22 = 1.f - 2.f*(x*x + y*y);

    // Cov = R^T diag(s^2) R (R orthogonal)  =>  CovInv = R^T diag(1/s^2) R
    float i0 = 1.f/(sx*sx), i1 = 1.f/(sy*sy), i2 = 1.f/(sz*sz);

    p.cxx = R00*R00*i0 + R10*R10*i1 + R20*R20*i2;
    p.cyy = R01*R01*i0 + R11*R11*i1 + R21*R21*i2;
    p.czz = R02*R02*i0 + R12*R12*i1 + R22*R22*i2;
    p.cxy = R00*R01*i0 + R10*R11*i1 + R20*R21*i2;
    p.cyz = R01*R02*i0 + R11*R12*i1 + R21*R22*i2;
    p.cxz = R00*R02*i0 + R10*R12*i1 + R20*R22*i2;

    float smax = fmaxf(sx, fmaxf(sy, sz));
    int rad = (int)ceilf(smax * 3.0f / VOXEL);
    if (rad < 1) rad = 1;
    if (rad > 3) rad = 3;   // offsets limited to +-3 in reference

    p.mix = (int)floorf((p.mx + 40.f) / VOXEL);
    p.miy = (int)floorf((p.my + 40.f) / VOXEL);
    p.miz = (int)floorf((p.mz +  1.f) / VOXEL);

    #pragma unroll
    for (int k = 0; k < FEAT_DIM; k++) p.f[k] = feats[FEAT_DIM*g + k];

    if      (rad == 1) splat_cells<1>(p, lane);
    else if (rad == 2) splat_cells<2>(p, lane);
    else               splat_cells<3>(p, lane);
}

// ---------------------------------------------------------------------------
// Finalize: out[0 : 640000]           = density
//           out[640000 + 17*v + k]    = feat_acc[v][k] / max(density, EPS)
// ---------------------------------------------------------------------------
__global__ void finalize_kernel(float* __restrict__ out) {
    int v = blockIdx.x * blockDim.x + threadIdx.x;
    if (v >= N_VOX) return;

    int col = v >> 4;       // ix*NVY + iy
    int iz  = v & 15;
    const float* base = g_accum + (size_t)col * COL_FLOATS + iz * 4;

    float4 a  = *reinterpret_cast<const float4*>(base);
    float4 b  = *reinterpret_cast<const float4*>(base +  64);
    float4 cc = *reinterpret_cast<const float4*>(base + 128);
    float4 dd = *reinterpret_cast<const float4*>(base + 192);
    float2 e  = *reinterpret_cast<const float2*>(base + 256);

    float d = e.y;
    out[v] = d;
    float inv = 1.f / fmaxf(d, 1e-6f);

    float* fo = out + N_VOX + (size_t)v * FEAT_DIM;
    fo[0]  = a.x  * inv;  fo[1]  = a.y  * inv;  fo[2]  = a.z  * inv;  fo[3]  = a.w  * inv;
    fo[4]  = b.x  * inv;  fo[5]  = b.y  * inv;  fo[6]  = b.z  * inv;  fo[7]  = b.w  * inv;
    fo[8]  = cc.x * inv;  fo[9]  = cc.y * inv;  fo[10] = cc.z * inv;  fo[11] = cc.w * inv;
    fo[12] = dd.x * inv;  fo[13] = dd.y * inv;  fo[14] = dd.z * inv;  fo[15] = dd.w * inv;
    fo[16] = e.x  * inv;
}

// ---------------------------------------------------------------------------
// Launch
// ---------------------------------------------------------------------------
extern "C" void kernel_launch(void* const* d_in, const int* in_sizes, int n_in,
                              void* d_out, int out_size) {
    const float* means  = (const float*)d_in[0];
    const float* opac   = (const float*)d_in[1];
    const float* scales = (const float*)d_in[2];
    const float* rots   = (const float*)d_in[3];
    const float* feats  = (const float*)d_in[4];
    int n = in_sizes[1];  // opacities: one per gaussian

    zero_kernel<<<2048, 256>>>();

    int threads = n * 32;                       // one warp per gaussian
    int blocks  = (threads + 255) / 256;
    splat_kernel<<<blocks, 256>>>(means, opac, scales, rots, feats, n);

    finalize_kernel<<<(N_VOX + 255) / 256, 256>>>((float*)d_out);
}